// round 2
// baseline (speedup 1.0000x reference)
#include <cuda_runtime.h>

// ---------------------------------------------------------------------------
// MixerBlock: token-mix (YAT + linear, residual) then channel-mix (YAT + linear, residual)
// Shapes: B=64, P=196, C=768, T_MLP=384, C_MLP=3072. All fp32.
// ---------------------------------------------------------------------------

#define EPSV 0.1f

// ---- scratch (device globals; no allocations allowed) ----
__device__ __align__(128) float g_H1[49152 * 384];   // (B*C, T_MLP)   75.5 MB
__device__ __align__(128) float g_X2[64 * 196 * 768]; // (B,P,C) after token mix  38.5 MB
__device__ __align__(128) float g_H3[12544 * 3072];  // (B*P, C_MLP)   154 MB
__device__ __align__(128) float g_xn1[49152];        // ||x_t||^2 per (b,c) row
__device__ __align__(128) float g_xn2[12544];        // ||X2||^2 per (b,p) row
__device__ __align__(128) float g_twn[384];          // ||tw_row||^2
__device__ __align__(128) float g_cwn[3072];         // ||cw_row||^2

// ---- packed f32x2 helpers (Blackwell FFMA2: 2x fp32 FMA throughput) ----
__device__ __forceinline__ void ffma2(unsigned long long &d,
                                      unsigned long long a,
                                      unsigned long long b) {
    asm("fma.rn.f32x2 %0, %1, %2, %0;" : "+l"(d) : "l"(a), "l"(b));
}
__device__ __forceinline__ unsigned long long pack2(float x) {
    unsigned long long r;
    unsigned u = __float_as_uint(x);
    asm("mov.b64 %0, {%1, %1};" : "=l"(r) : "r"(u));
    return r;
}

// ---------------------------------------------------------------------------
// Row-norm helper: dst[row] = sum_k src[row*K+k]^2   (warp per row)
// sel: 0 -> g_twn, 1 -> g_cwn, 2 -> g_xn2 with src = g_X2
// ---------------------------------------------------------------------------
__global__ void rownorm_kernel(const float* __restrict__ srcArg, int rows, int K, int sel) {
    const float* src = (sel == 2) ? g_X2 : srcArg;
    float* dst = (sel == 0) ? g_twn : (sel == 1) ? g_cwn : g_xn2;
    int row = blockIdx.x * 4 + (threadIdx.x >> 5);
    if (row >= rows) return;
    int lane = threadIdx.x & 31;
    const float* p = src + (long)row * K;
    float s = 0.f;
    for (int k = lane; k < K; k += 32) { float v = p[k]; s = fmaf(v, v, s); }
#pragma unroll
    for (int o = 16; o; o >>= 1) s += __shfl_xor_sync(0xffffffffu, s, o);
    if (lane == 0) dst[row] = s;
}

// x norms over the patch dim: g_xn1[b*768+c] = sum_p x[b,p,c]^2
__global__ void xnorm1_kernel(const float* __restrict__ x) {
    int g = blockIdx.x * blockDim.x + threadIdx.x;   // < 49152
    int b = g / 768, c = g - b * 768;
    const float* p = x + (long)b * 196 * 768 + c;
    float s = 0.f;
#pragma unroll 4
    for (int i = 0; i < 196; ++i) { float v = p[(long)i * 768]; s = fmaf(v, v, s); }
    g_xn1[g] = s;
}

// ---------------------------------------------------------------------------
// Fused GEMM (128x128 tile, BK=8, 256 threads, 8x8 micro-tile via f32x2).
//   C[m,n] = sum_k A[m,k] * W[n,k]          (W row-major (N,K))
// MODE 0: A = x (transposed access, m=(b,c), k=p), epilogue = token YAT -> g_H1
// MODE 1: A = g_H1, epilogue = residual + transpose -> g_X2[(b,p,c)] (n=p)
// MODE 2: A = g_X2, epilogue = channel YAT -> g_H3
// MODE 3: A = g_H3, epilogue = residual -> out (row-major)
// ---------------------------------------------------------------------------
template<int MODE>
__global__ __launch_bounds__(256, 2) void gemm_kernel(
    const float* __restrict__ Aarg,
    const float* __restrict__ W,
    const float* __restrict__ bias,
    const float* __restrict__ alpha,
    const float* __restrict__ resArg,
    float* __restrict__ outArg)
{
    constexpr int N  = (MODE == 0) ? 384 : (MODE == 1) ? 196 : (MODE == 2) ? 3072 : 768;
    constexpr int K  = (MODE == 0) ? 196 : (MODE == 1) ? 384 : (MODE == 2) ? 768 : 3072;
    constexpr int KT = (K + 7) / 8;
    constexpr bool KRAG = (K % 8) != 0;    // only MODE 0
    constexpr bool NRAG = (N % 128) != 0;  // only MODE 1

    const float* A = (MODE == 0) ? Aarg : (MODE == 1) ? g_H1 : (MODE == 2) ? g_X2 : g_H3;
    float* out = (MODE == 0) ? g_H1 : (MODE == 1) ? g_X2 : (MODE == 2) ? g_H3 : outArg;

    __shared__ float As[2][8][132];
    __shared__ float Bs[2][8][132];

    const int tid = threadIdx.x;
    const int m0 = blockIdx.y * 128;
    const int n0 = blockIdx.x * 128;

    // ---- B global-load mapping (transpose (N,K) row-major -> Bs[k][n]) ----
    const int bn  = tid >> 1;
    const int bk4 = (tid & 1) * 4;
    const int gnb = n0 + bn;
    const bool bnOK = !NRAG || (gnb < N);
    const float* Bptr = W + (long)gnb * K + bk4;

    // ---- A global-load mapping ----
    int a_kk, a_mm;
    const float* Aptr;
    if (MODE == 0) {
        a_kk = tid >> 5;              // 0..7
        a_mm = (tid & 31) * 4;        // 0..124
        const int b = m0 / 768;
        const int c = (m0 % 768) + a_mm;
        Aptr = A + ((long)(b * 196 + a_kk)) * 768 + c;   // advance by 8*768 per kt
    } else {
        a_mm = tid >> 1;              // 0..127
        a_kk = (tid & 1) * 4;         // 0 or 4
        Aptr = A + (long)(m0 + a_mm) * K + a_kk;          // advance by 8 per kt
    }

    const int tx = tid & 15;
    const int ty = tid >> 4;

    unsigned long long acc[8][4];
#pragma unroll
    for (int i = 0; i < 8; ++i)
#pragma unroll
        for (int j = 0; j < 4; ++j) acc[i][j] = 0ull;

    auto ldA = [&](int kt) -> float4 {
        if (MODE == 0) {
            if (!KRAG || (kt * 8 + a_kk) < K)
                return *(const float4*)(Aptr + (long)kt * 8 * 768);
            return make_float4(0.f, 0.f, 0.f, 0.f);
        } else {
            return *(const float4*)(Aptr + kt * 8);
        }
    };
    auto ldB = [&](int kt) -> float4 {
        bool ok = bnOK && (!KRAG || (kt * 8 + bk4) < K);
        if (ok) return *(const float4*)(Bptr + kt * 8);
        return make_float4(0.f, 0.f, 0.f, 0.f);
    };
    auto stA = [&](int bu, float4 v) {
        if (MODE == 0) {
            *(float4*)&As[bu][a_kk][a_mm] = v;
        } else {
            As[bu][a_kk + 0][a_mm] = v.x; As[bu][a_kk + 1][a_mm] = v.y;
            As[bu][a_kk + 2][a_mm] = v.z; As[bu][a_kk + 3][a_mm] = v.w;
        }
    };
    auto stB = [&](int bu, float4 v) {
        Bs[bu][bk4 + 0][bn] = v.x; Bs[bu][bk4 + 1][bn] = v.y;
        Bs[bu][bk4 + 2][bn] = v.z; Bs[bu][bk4 + 3][bn] = v.w;
    };

    stA(0, ldA(0));
    stB(0, ldB(0));
    __syncthreads();

    int buf = 0;
    for (int kt = 0; kt < KT; ++kt) {
        float4 na, nb4;
        const bool more = (kt + 1 < KT);
        if (more) { na = ldA(kt + 1); nb4 = ldB(kt + 1); }

#pragma unroll
        for (int kk = 0; kk < 8; ++kk) {
            float4 a0 = *(const float4*)&As[buf][kk][ty * 4];
            float4 a1 = *(const float4*)&As[buf][kk][64 + ty * 4];
            ulonglong2 bv0 = *(const ulonglong2*)&Bs[buf][kk][tx * 4];
            ulonglong2 bv1 = *(const ulonglong2*)&Bs[buf][kk][64 + tx * 4];
            float av[8] = {a0.x, a0.y, a0.z, a0.w, a1.x, a1.y, a1.z, a1.w};
#pragma unroll
            for (int i = 0; i < 8; ++i) {
                unsigned long long ap = pack2(av[i]);
                ffma2(acc[i][0], ap, bv0.x);
                ffma2(acc[i][1], ap, bv0.y);
                ffma2(acc[i][2], ap, bv1.x);
                ffma2(acc[i][3], ap, bv1.y);
            }
        }

        if (more) {
            stA(buf ^ 1, na);
            stB(buf ^ 1, nb4);
            __syncthreads();
            buf ^= 1;
        }
    }

    // ---- unpack accumulators: cfr[i][0..3] = n0+tx*4+{0..3}; [4..7] = n0+64+tx*4+{0..3} ----
    float cfr[8][8];
#pragma unroll
    for (int i = 0; i < 8; ++i)
#pragma unroll
        for (int j = 0; j < 4; ++j) {
            cfr[i][2 * j]     = __uint_as_float((unsigned)acc[i][j]);
            cfr[i][2 * j + 1] = __uint_as_float((unsigned)(acc[i][j] >> 32));
        }

    int mrow[8];
#pragma unroll
    for (int i = 0; i < 8; ++i) mrow[i] = m0 + ((i < 4) ? ty * 4 + i : 64 + ty * 4 + i - 4);
    const int ncol0 = n0 + tx * 4;
    const int ncol1 = n0 + 64 + tx * 4;

    if constexpr (MODE == 0 || MODE == 2) {
        // YAT epilogue: scale * (dot+b)^2 / (||w||^2 + ||x||^2 - 2*dot + eps)
        const float* wn = (MODE == 0) ? g_twn : g_cwn;
        const float* xn = (MODE == 0) ? g_xn1 : g_xn2;
        const float sc = powf(sqrtf((float)N / logf((float)N + 1.0f)), alpha[0]);
        float xv[8];
#pragma unroll
        for (int i = 0; i < 8; ++i) xv[i] = xn[mrow[i]];
#pragma unroll
        for (int jg = 0; jg < 2; ++jg) {
            const int nb0 = jg ? ncol1 : ncol0;
            float wv[4], bv[4];
#pragma unroll
            for (int jj = 0; jj < 4; ++jj) { wv[jj] = wn[nb0 + jj]; bv[jj] = bias[nb0 + jj]; }
#pragma unroll
            for (int i = 0; i < 8; ++i) {
                float4 r;
                float* rp = (float*)&r;
#pragma unroll
                for (int jj = 0; jj < 4; ++jj) {
                    float d  = cfr[i][jg * 4 + jj];
                    float dt = d + bv[jj];
                    float ds = wv[jj] + xv[i] - 2.0f * d + EPSV;
                    rp[jj] = sc * dt * dt / ds;
                }
                *(float4*)&out[(long)mrow[i] * N + nb0] = r;
            }
        }
    }

    if constexpr (MODE == 1) {
        // residual + transpose: X2[(b,p=n,c)] = x + acc + b2[n]; m=(b,c)
        const float* res = resArg;   // x
        const int bidx = m0 / 768;
#pragma unroll
        for (int ig = 0; ig < 2; ++ig) {
            const int mstart = m0 + (ig ? 64 : 0) + ty * 4;
            const int cc = mstart % 768;
#pragma unroll
            for (int j = 0; j < 8; ++j) {
                const int ngl = (j < 4) ? (n0 + tx * 4 + j) : (n0 + 64 + tx * 4 + j - 4);
                if (!NRAG || ngl < N) {
                    const long o = ((long)(bidx * 196 + ngl)) * 768 + cc;
                    float4 xv4 = *(const float4*)&res[o];
                    const float bj = bias[ngl];
                    float4 r;
                    r.x = xv4.x + cfr[ig * 4 + 0][j] + bj;
                    r.y = xv4.y + cfr[ig * 4 + 1][j] + bj;
                    r.z = xv4.z + cfr[ig * 4 + 2][j] + bj;
                    r.w = xv4.w + cfr[ig * 4 + 3][j] + bj;
                    *(float4*)&out[o] = r;
                }
            }
        }
    }

    if constexpr (MODE == 3) {
        // residual, row-major: out[m,n] = X2[m,n] + acc + b4[n]
        const float* res = g_X2;
#pragma unroll
        for (int i = 0; i < 8; ++i) {
#pragma unroll
            for (int jg = 0; jg < 2; ++jg) {
                const int nb0 = jg ? ncol1 : ncol0;
                const long o = (long)mrow[i] * N + nb0;
                float4 rv = *(const float4*)&res[o];
                float4 r;
                r.x = rv.x + cfr[i][jg * 4 + 0] + bias[nb0 + 0];
                r.y = rv.y + cfr[i][jg * 4 + 1] + bias[nb0 + 1];
                r.z = rv.z + cfr[i][jg * 4 + 2] + bias[nb0 + 2];
                r.w = rv.w + cfr[i][jg * 4 + 3] + bias[nb0 + 3];
                *(float4*)&out[o] = r;
            }
        }
    }
}

// ---------------------------------------------------------------------------
extern "C" void kernel_launch(void* const* d_in, const int* in_sizes, int n_in,
                              void* d_out, int out_size) {
    (void)in_sizes; (void)n_in; (void)out_size;
    const float* x  = (const float*)d_in[0];
    const float* tw = (const float*)d_in[1];
    const float* tb = (const float*)d_in[2];
    const float* ta = (const float*)d_in[3];
    const float* w2 = (const float*)d_in[4];
    const float* b2 = (const float*)d_in[5];
    const float* cw = (const float*)d_in[6];
    const float* cb = (const float*)d_in[7];
    const float* ca = (const float*)d_in[8];
    const float* w4 = (const float*)d_in[9];
    const float* b4 = (const float*)d_in[10];
    float* outp = (float*)d_out;

    // weight norms + x norms (token path)
    rownorm_kernel<<<96, 128>>>(tw, 384, 196, 0);     // g_twn
    rownorm_kernel<<<768, 128>>>(cw, 3072, 768, 1);   // g_cwn
    xnorm1_kernel<<<192, 256>>>(x);                   // g_xn1

    // token mixing
    gemm_kernel<0><<<dim3(3, 384), 256>>>(x, tw, tb, ta, nullptr, nullptr);        // -> g_H1
    gemm_kernel<1><<<dim3(2, 384), 256>>>(nullptr, w2, b2, nullptr, x, nullptr);   // -> g_X2

    // channel mixing
    rownorm_kernel<<<3136, 128>>>(nullptr, 12544, 768, 2);                          // g_xn2
    gemm_kernel<2><<<dim3(24, 98), 256>>>(nullptr, cw, cb, ca, nullptr, nullptr);   // -> g_H3
    gemm_kernel<3><<<dim3(6, 98), 256>>>(nullptr, w4, b4, nullptr, nullptr, outp);  // -> out
}